// round 6
// baseline (speedup 1.0000x reference)
#include <cuda_runtime.h>
#include <math.h>

// GradientHistLoss — persistent kernel, 148x1024, 5 grid syncs.
//  P1  all blocks: per-block top-11-bit hist of gt -> slots
//  P2  blocks 0-3: combine + locate ranks k,k+1; zero candidate counters.
//      blocks 4+ : prefetch pred into L2.
//  P3  all blocks: collect candidate keys (top bin b0 / b1) via
//      warp-aggregated global atomics.
//  P4  blocks 0-3: block-local exact select (mid 11 bits, low 10 bits)
//      over candidates -> invbw.
//  P5  all blocks: triangular soft hists (pred+gt) -> per-block slots.
//  P6  block 0: combine + weighted-L1 finalize -> out.

#define NBINS    64
#define BATCH    4
#define NBLOCKS  148
#define NTHREADS 1024
#define SBLKS    37
#define RTOP     2048
#define RMID     2048
#define RLOW     1024
#define CAP      294912
#define SKIP     0xFFFFFFFFu
#define FULLM    0xFFFFFFFFu

// ---- device scratch ----
__device__ unsigned g_top[NBLOCKS][RTOP];
__device__ unsigned g_tinfo[BATCH][4];        // b0, rem0, b1, rem1
__device__ unsigned g_cand[BATCH][2][CAP];
__device__ unsigned g_ccnt[BATCH][2];         // zeroed in P2 each call
__device__ float    g_invbw[BATCH];
__device__ float    g_softb[NBLOCKS][2 * NBINS];
__device__ unsigned g_dummy[NBLOCKS];
__device__ unsigned          g_bar_count;
__device__ volatile unsigned g_bar_gen;

// -------------------------------------------------------------------------
__device__ __forceinline__ void grid_sync() {
    __syncthreads();
    if (threadIdx.x == 0) {
        __threadfence();
        unsigned gen = g_bar_gen;
        if (atomicAdd(&g_bar_count, 1u) == NBLOCKS - 1) {
            g_bar_count = 0u;
            __threadfence();
            g_bar_gen = gen + 1u;
        } else {
            while (g_bar_gen == gen) { }       // tight spin (L2 poll)
        }
        __threadfence();
    }
    __syncthreads();
}

// Block-collective: locate ranks r0 (and r1 unless SKIP) in cnt[0..bins).
// Results in s_loc = {bin0, rem0, bin1, rem1}.
__device__ void locate2(const unsigned* cnt, int bins, unsigned r0, unsigned r1,
                        unsigned* s_ws, unsigned* s_loc) {
    int tid = threadIdx.x, lane = tid & 31, warp = tid >> 5;
    int per = bins >> 10;                  // 1 or 2
    unsigned base = tid * per, sum = 0u;
    #pragma unroll
    for (int i = 0; i < 2; i++) if (i < per) sum += cnt[base + i];
    unsigned incl = sum;
    #pragma unroll
    for (int o = 1; o < 32; o <<= 1) {
        unsigned v = __shfl_up_sync(FULLM, incl, o);
        if (lane >= o) incl += v;
    }
    if (lane == 31) s_ws[warp] = incl;
    __syncthreads();
    if (warp == 0) {
        unsigned v = s_ws[lane], wi = v;
        #pragma unroll
        for (int o = 1; o < 32; o <<= 1) {
            unsigned t = __shfl_up_sync(FULLM, wi, o);
            if (lane >= o) wi += t;
        }
        s_ws[lane] = wi - v;
    }
    __syncthreads();
    unsigned inclT = incl + s_ws[warp];
    unsigned exclT = inclT - sum;
    #pragma unroll
    for (int j = 0; j < 2; j++) {
        unsigned r = (j == 0) ? r0 : r1;
        if (r != SKIP && exclT <= r && r < inclT) {
            unsigned local = r - exclT, d = base;
            while (local >= cnt[d]) { local -= cnt[d]; d++; }
            s_loc[2 * j] = d;
            s_loc[2 * j + 1] = local;
        }
    }
    __syncthreads();
}

// Warp-aggregated push of matching keys into buf (global counter ctr).
__device__ __forceinline__ void wpush(bool m, unsigned key,
                                      unsigned* ctr, unsigned* buf, int lane) {
    unsigned bal = __ballot_sync(FULLM, m);
    if (bal) {
        int leader = __ffs(bal) - 1;
        unsigned pos = 0;
        if (lane == leader) pos = atomicAdd(ctr, (unsigned)__popc(bal));
        pos = __shfl_sync(FULLM, pos, leader);
        if (m) buf[pos + __popc(bal & ((1u << lane) - 1u))] = key;
    }
}

// -------------------------------------------------------------------------
__global__ void __launch_bounds__(NTHREADS, 1)
ghl_kernel(const float* __restrict__ pred, const float* __restrict__ gt,
           int nper, unsigned k, float frac, float* __restrict__ out) {
    __shared__ unsigned sh[2 * RMID];      // 16KB scratch (reused per phase)
    __shared__ unsigned s_ws[32];
    __shared__ unsigned s_loc[4];
    __shared__ float    s_red[BATCH];

    int tid  = threadIdx.x;
    int lane = tid & 31;
    int warp = tid >> 5;
    int bx   = blockIdx.x;
    int samp = bx & 3;
    int sblk = bx >> 2;
    const float*  gb = gt + (size_t)samp * nper;
    const float4* g4 = (const float4*)gb;
    int nq    = nper >> 2;
    int i0    = sblk * NTHREADS + tid;
    int istr  = SBLKS * NTHREADS;
    int tail0 = (nq << 2) + i0;

    // ================= P1: per-block top-11-bit hist ======================
    for (int i = tid; i < RTOP; i += NTHREADS) sh[i] = 0u;
    __syncthreads();
    for (int i = i0; i < nq; i += istr) {
        float4 v = g4[i];
        atomicAdd(&sh[__float_as_uint(v.x) >> 21], 1u);
        atomicAdd(&sh[__float_as_uint(v.y) >> 21], 1u);
        atomicAdd(&sh[__float_as_uint(v.z) >> 21], 1u);
        atomicAdd(&sh[__float_as_uint(v.w) >> 21], 1u);
    }
    for (int i = tail0; i < nper; i += istr)
        atomicAdd(&sh[__float_as_uint(gb[i]) >> 21], 1u);
    __syncthreads();
    {
        uint4* dst = (uint4*)g_top[bx];
        const uint4* src = (const uint4*)sh;
        for (int i = tid; i < RTOP / 4; i += NTHREADS) dst[i] = src[i];
    }
    grid_sync();

    // ================= P2: combine+locate (0-3) / prefetch pred (4+) =====
    if (bx < BATCH) {
        if (tid < 2) g_ccnt[bx][tid] = 0u;
        for (int i = tid; i < RTOP; i += NTHREADS) {
            unsigned s = 0u;
            #pragma unroll 8
            for (int j = 0; j < SBLKS; j++) s += g_top[4 * j + bx][i];
            sh[i] = s;
        }
        __syncthreads();
        locate2(sh, RTOP, k, k + 1u, s_ws, s_loc);
        if (tid == 0) {
            g_tinfo[bx][0] = s_loc[0]; g_tinfo[bx][1] = s_loc[1];
            g_tinfo[bx][2] = s_loc[2]; g_tinfo[bx][3] = s_loc[3];
        }
    } else {
        // prefetch all of pred into L2
        const uint4* pp = (const uint4*)pred;
        int quads = (nper * BATCH) >> 2;
        unsigned acc = 0u;
        for (int i = (bx - BATCH) * NTHREADS + tid; i < quads;
             i += (NBLOCKS - BATCH) * NTHREADS) {
            uint4 v = pp[i];
            acc ^= v.x ^ v.y ^ v.z ^ v.w;
        }
        g_dummy[bx] = acc;
    }
    grid_sync();

    // ================= P3: collect candidates (warp-aggregated) ==========
    unsigned b0 = g_tinfo[samp][0], b1 = g_tinfo[samp][2];
    bool use2 = (b0 != b1);
    {
        int wbase0 = sblk * NTHREADS + warp * 32;
        for (int base = wbase0; base < nq; base += istr) {
            int i = base + lane;
            bool v = (i < nq);
            float4 val;
            if (v) val = g4[i];
            unsigned kk[4] = {v ? __float_as_uint(val.x) : 0u,
                              v ? __float_as_uint(val.y) : 0u,
                              v ? __float_as_uint(val.z) : 0u,
                              v ? __float_as_uint(val.w) : 0u};
            #pragma unroll
            for (int c = 0; c < 4; c++) {
                unsigned t = kk[c] >> 21;
                wpush(v && t == b0, kk[c], &g_ccnt[samp][0], g_cand[samp][0], lane);
                if (use2)
                    wpush(v && t == b1, kk[c], &g_ccnt[samp][1], g_cand[samp][1], lane);
            }
        }
        for (int base = (nq << 2) + wbase0; base < nper; base += istr) {
            int i = base + lane;
            bool v = (i < nper);
            unsigned kk = v ? __float_as_uint(gb[i]) : 0u;
            unsigned t = kk >> 21;
            wpush(v && t == b0, kk, &g_ccnt[samp][0], g_cand[samp][0], lane);
            if (use2)
                wpush(v && t == b1, kk, &g_ccnt[samp][1], g_cand[samp][1], lane);
        }
    }
    grid_sync();

    // ================= P4: exact select over candidates (blocks 0-3) =====
    if (bx < BATCH) {
        unsigned B0 = g_tinfo[bx][0], R0 = g_tinfo[bx][1];
        unsigned B1 = g_tinfo[bx][2], R1 = g_tinfo[bx][3];
        bool two = (B0 != B1);
        unsigned c0 = g_ccnt[bx][0];
        unsigned c1 = two ? g_ccnt[bx][1] : 0u;
        const unsigned* buf0 = g_cand[bx][0];
        const unsigned* buf1 = g_cand[bx][1];

        // ---- mid level (11 bits) ----
        for (int i = tid; i < 2 * RMID; i += NTHREADS) sh[i] = 0u;
        __syncthreads();
        for (unsigned i = tid; i < c0; i += NTHREADS)
            atomicAdd(&sh[(buf0[i] >> 10) & 0x7FFu], 1u);
        if (two)
            for (unsigned i = tid; i < c1; i += NTHREADS)
                atomicAdd(&sh[RMID + ((buf1[i] >> 10) & 0x7FFu)], 1u);
        __syncthreads();
        unsigned m0, rm0, m1, rm1;
        if (!two) {
            locate2(sh, RMID, R0, R1, s_ws, s_loc);
            m0 = s_loc[0]; rm0 = s_loc[1];
            m1 = s_loc[2]; rm1 = s_loc[3];
        } else {
            locate2(sh, RMID, R0, SKIP, s_ws, s_loc);
            m0 = s_loc[0]; rm0 = s_loc[1];
            locate2(sh + RMID, RMID, R1, SKIP, s_ws, s_loc);
            m1 = s_loc[0]; rm1 = s_loc[1];
        }
        __syncthreads();

        // ---- low level (10 bits) ----
        for (int i = tid; i < 2 * RLOW; i += NTHREADS) sh[i] = 0u;
        __syncthreads();
        for (unsigned i = tid; i < c0; i += NTHREADS) {
            unsigned kk = buf0[i];
            if (((kk >> 10) & 0x7FFu) == m0) atomicAdd(&sh[kk & 0x3FFu], 1u);
        }
        {
            const unsigned* bufX = two ? buf1 : buf0;
            unsigned cX = two ? c1 : c0;
            for (unsigned i = tid; i < cX; i += NTHREADS) {
                unsigned kk = bufX[i];
                if (((kk >> 10) & 0x7FFu) == m1)
                    atomicAdd(&sh[RLOW + (kk & 0x3FFu)], 1u);
            }
        }
        __syncthreads();
        unsigned d0, d1;
        if (!two && m0 == m1) {
            locate2(sh, RLOW, rm0, rm1, s_ws, s_loc);
            d0 = s_loc[0]; d1 = s_loc[2];
        } else {
            locate2(sh, RLOW, rm0, SKIP, s_ws, s_loc);
            d0 = s_loc[0];
            locate2(sh + RLOW, RLOW, rm1, SKIP, s_ws, s_loc);
            d1 = s_loc[0];
        }
        if (tid == 0) {
            float v0 = __uint_as_float((B0 << 21) | (m0 << 10) | d0);
            float v1 = __uint_as_float((B1 << 21) | (m1 << 10) | d1);
            float mv = v0 + frac * (v1 - v0);
            g_invbw[bx] = (mv > 0.0f) ? (float)NBINS / mv : 0.0f;
        }
    }
    grid_sync();

    // ================= P5: soft hists (4 replicated shared copies) =======
    {
        float invbw = g_invbw[samp];
        float* shf = (float*)sh;
        for (int i = tid; i < 4 * 2 * NBINS; i += NTHREADS) shf[i] = 0.0f;
        __syncthreads();
        float* my = shf + (warp & 3) * 2 * NBINS;
        const float4* p4 = (const float4*)(pred + (size_t)samp * nper);
        for (int i = i0; i < nq; i += istr) {
            float4 pv = p4[i];
            float4 gv = g4[i];
            float pe[4] = {pv.x, pv.y, pv.z, pv.w};
            float ge[4] = {gv.x, gv.y, gv.z, gv.w};
            #pragma unroll
            for (int c = 0; c < 4; c++) {
                float up = pe[c] * invbw;
                int   jp = (int)floorf(up);
                float fp = up - (float)jp;
                if (jp >= 0 && jp < NBINS) {
                    atomicAdd(&my[jp], 1.0f - fp);
                    if (jp + 1 < NBINS) atomicAdd(&my[jp + 1], fp);
                }
                float ug = ge[c] * invbw;
                int   jg = (int)floorf(ug);
                float fg = ug - (float)jg;
                if (jg >= 0 && jg < NBINS) {
                    atomicAdd(&my[NBINS + jg], 1.0f - fg);
                    if (jg + 1 < NBINS) atomicAdd(&my[NBINS + jg + 1], fg);
                }
            }
        }
        const float* pb = pred + (size_t)samp * nper;
        for (int i = tail0; i < nper; i += istr) {
            float up = pb[i] * invbw;
            int   jp = (int)floorf(up);
            float fp = up - (float)jp;
            if (jp >= 0 && jp < NBINS) {
                atomicAdd(&my[jp], 1.0f - fp);
                if (jp + 1 < NBINS) atomicAdd(&my[jp + 1], fp);
            }
            float ug = gb[i] * invbw;
            int   jg = (int)floorf(ug);
            float fg = ug - (float)jg;
            if (jg >= 0 && jg < NBINS) {
                atomicAdd(&my[NBINS + jg], 1.0f - fg);
                if (jg + 1 < NBINS) atomicAdd(&my[NBINS + jg + 1], fg);
            }
        }
        __syncthreads();
        for (int i = tid; i < 2 * NBINS; i += NTHREADS)
            g_softb[bx][i] = shf[i] + shf[128 + i] + shf[256 + i] + shf[384 + i];
    }
    grid_sync();

    // ================= P6: finalize (block 0) =============================
    if (bx == 0) {
        float* s_h = (float*)sh;           // 512 floats: [b][0..127]
        if (tid < BATCH * 2 * NBINS) {
            int b = tid >> 7, idx = tid & 127;
            float s = 0.0f;
            #pragma unroll 8
            for (int j = 0; j < SBLKS; j++) s += g_softb[4 * j + b][idx];
            s_h[tid] = s;
        }
        __syncthreads();
        if (warp < BATCH) {
            int b = warp;
            float sp = s_h[b * 128 + lane] + s_h[b * 128 + 32 + lane];
            float sg = s_h[b * 128 + 64 + lane] + s_h[b * 128 + 96 + lane];
            #pragma unroll
            for (int o = 16; o >= 1; o >>= 1) {
                sp += __shfl_xor_sync(FULLM, sp, o);
                sg += __shfl_xor_sync(FULLM, sg, o);
            }
            float acc = 0.0f;
            #pragma unroll
            for (int h = 0; h < 2; h++) {
                int j = h * 32 + lane;
                float bw = expf(0.4f * (float)j / (float)NBINS);
                float p = s_h[b * 128 + j];
                float g = s_h[b * 128 + 64 + j];
                acc += fabsf(p / sp - g / sg) * bw;
            }
            #pragma unroll
            for (int o = 16; o >= 1; o >>= 1)
                acc += __shfl_xor_sync(FULLM, acc, o);
            if (lane == 0) s_red[b] = acc * (1.0f / (float)NBINS);
        }
        __syncthreads();
        if (tid == 0)
            out[0] = (s_red[0] + s_red[1] + s_red[2] + s_red[3]) *
                     (1.0f / (float)BATCH);
    }
}

// -------------------------------------------------------------------------
extern "C" void kernel_launch(void* const* d_in, const int* in_sizes, int n_in,
                              void* d_out, int out_size) {
    const float* pred = (const float*)d_in[0];
    const float* gt   = (const float*)d_in[1];
    int ntot = in_sizes[0];
    int nper = ntot / BATCH;

    double pos = 0.95 * (double)(nper - 1);
    unsigned k = (unsigned)pos;
    float frac = (float)(pos - (double)k);

    ghl_kernel<<<NBLOCKS, NTHREADS>>>(pred, gt, nper, k, frac, (float*)d_out);
}

// round 9
// speedup vs baseline: 1.3414x; 1.3414x over previous
#include <cuda_runtime.h>
#include <math.h>

// GradientHistLoss — persistent kernel, 148x1024, 32KB static smem, 5 syncs.
//  P1  all: 13-bit (8192-bin) shared hist of gt; sparse global-RED flush.
//  P2  blk 0-3: locate ranks k,k+1 on global hist; re-zero hist, soft acc,
//      cand counters.  blk 4+: prefetch pred into L2.
//  P3  all: collect candidate keys (13-bit prefix match, ~3%) via
//      warp-aggregated pushes.
//  P4  blk 0-7 (one per sample x rank): exact select over candidates
//      (11-bit + 8-bit levels) -> g_val.
//  P5  all: triangular soft hists (pred+gt), flush via global float RED.
//  P6  blk 0: weighted-L1 finalize -> out.

#define NBINS    64
#define BATCH    4
#define NBLOCKS  148
#define NTHREADS 1024
#define SBLKS    37
#define H1BINS   8192         // key >> 19
#define RA       2048         // (key >> 8) & 0x7FF
#define RB       256          // key & 0xFF
#define CAP      294912
#define SKIP     0xFFFFFFFFu
#define FULLM    0xFFFFFFFFu

// ---- device scratch ----
__device__ unsigned g_h1[BATCH][H1BINS];       // zero at load; re-zeroed in P2
__device__ unsigned g_tinfo[BATCH][4];         // b0, rem0, b1, rem1
__device__ unsigned g_cand[BATCH][2][CAP];
__device__ unsigned g_ccnt[BATCH][2];
__device__ float    g_val[BATCH][2];
__device__ float    g_softG[BATCH][2 * NBINS]; // zeroed in P2
__device__ unsigned g_dummy[NBLOCKS];
__device__ unsigned          g_bar_count;
__device__ volatile unsigned g_bar_gen;

// -------------------------------------------------------------------------
__device__ __forceinline__ void grid_sync() {
    __syncthreads();
    if (threadIdx.x == 0) {
        __threadfence();
        unsigned gen = g_bar_gen;
        if (atomicAdd(&g_bar_count, 1u) == NBLOCKS - 1) {
            g_bar_count = 0u;
            __threadfence();
            g_bar_gen = gen + 1u;
        } else {
            while (g_bar_gen == gen) { __nanosleep(20); }
        }
        __threadfence();
    }
    __syncthreads();
}

// Block-collective: locate ranks r0 (and r1 unless SKIP) in cnt[0..bins).
__device__ void locate2(const unsigned* cnt, int bins, unsigned r0, unsigned r1,
                        unsigned* s_ws, unsigned* s_loc) {
    int tid = threadIdx.x, lane = tid & 31, warp = tid >> 5;
    int per = (bins + NTHREADS - 1) / NTHREADS;
    int base = tid * per;
    unsigned sum = 0u;
    for (int i = 0; i < per; i++) {
        int idx = base + i;
        if (idx < bins) sum += cnt[idx];
    }
    unsigned incl = sum;
    #pragma unroll
    for (int o = 1; o < 32; o <<= 1) {
        unsigned v = __shfl_up_sync(FULLM, incl, o);
        if (lane >= o) incl += v;
    }
    if (lane == 31) s_ws[warp] = incl;
    __syncthreads();
    if (warp == 0) {
        unsigned v = s_ws[lane], wi = v;
        #pragma unroll
        for (int o = 1; o < 32; o <<= 1) {
            unsigned t = __shfl_up_sync(FULLM, wi, o);
            if (lane >= o) wi += t;
        }
        s_ws[lane] = wi - v;
    }
    __syncthreads();
    unsigned inclT = incl + s_ws[warp];
    unsigned exclT = inclT - sum;
    #pragma unroll
    for (int j = 0; j < 2; j++) {
        unsigned r = (j == 0) ? r0 : r1;
        if (r != SKIP && exclT <= r && r < inclT) {
            unsigned local = r - exclT;
            int d = base;
            while (local >= cnt[d]) { local -= cnt[d]; d++; }
            s_loc[2 * j] = (unsigned)d;
            s_loc[2 * j + 1] = local;
        }
    }
    __syncthreads();
}

// Warp-aggregated push of matching keys into buf (global counter ctr).
__device__ __forceinline__ void wpush(bool m, unsigned key,
                                      unsigned* ctr, unsigned* buf, int lane) {
    unsigned bal = __ballot_sync(FULLM, m);
    if (bal) {
        int leader = __ffs(bal) - 1;
        unsigned pos = 0;
        if (lane == leader) pos = atomicAdd(ctr, (unsigned)__popc(bal));
        pos = __shfl_sync(FULLM, pos, leader);
        if (m) buf[pos + __popc(bal & ((1u << lane) - 1u))] = key;
    }
}

__device__ __forceinline__ void hist4(unsigned* sh, float4 v) {
    atomicAdd(&sh[__float_as_uint(v.x) >> 19], 1u);
    atomicAdd(&sh[__float_as_uint(v.y) >> 19], 1u);
    atomicAdd(&sh[__float_as_uint(v.z) >> 19], 1u);
    atomicAdd(&sh[__float_as_uint(v.w) >> 19], 1u);
}

// -------------------------------------------------------------------------
__global__ void __launch_bounds__(NTHREADS, 1)
ghl_kernel(const float* __restrict__ pred, const float* __restrict__ gt,
           int nper, unsigned k, float frac, float* __restrict__ out) {
    __shared__ unsigned sh[H1BINS];        // 32KB static, reused per phase
    __shared__ unsigned s_ws[32];
    __shared__ unsigned s_loc[4];
    __shared__ float    s_red[BATCH];

    int tid  = threadIdx.x;
    int lane = tid & 31;
    int warp = tid >> 5;
    int bx   = blockIdx.x;
    int samp = bx & 3;
    int sblk = bx >> 2;
    const float*  gb = gt + (size_t)samp * nper;
    const float4* g4 = (const float4*)gb;
    int nq    = nper >> 2;
    int i0    = sblk * NTHREADS + tid;
    int istr  = SBLKS * NTHREADS;
    int tail0 = (nq << 2) + i0;

    // ================= P1: 13-bit shared hist of gt, sparse flush =========
    for (int i = tid; i < H1BINS; i += NTHREADS) sh[i] = 0u;
    __syncthreads();
    for (int i = i0; i < nq; i += 2 * istr) {
        float4 a = g4[i];
        int ib = i + istr;
        bool hb = ib < nq;
        float4 b;
        if (hb) b = g4[ib];
        hist4(sh, a);
        if (hb) hist4(sh, b);
    }
    for (int i = tail0; i < nper; i += istr)
        atomicAdd(&sh[__float_as_uint(gb[i]) >> 19], 1u);
    __syncthreads();
    for (int i = tid; i < H1BINS; i += NTHREADS) {
        unsigned v = sh[i];
        if (v) atomicAdd(&g_h1[samp][i], v);
    }
    grid_sync();

    // ================= P2: locate (0-3) / prefetch pred (4+) =============
    if (bx < BATCH) {
        locate2(g_h1[bx], H1BINS, k, k + 1u, s_ws, s_loc);
        if (tid == 0) {
            g_tinfo[bx][0] = s_loc[0]; g_tinfo[bx][1] = s_loc[1];
            g_tinfo[bx][2] = s_loc[2]; g_tinfo[bx][3] = s_loc[3];
        }
        if (tid < 2) g_ccnt[bx][tid] = 0u;
        {   // re-zero histogram for next call
            uint4 z = {0u, 0u, 0u, 0u};
            uint4* h4 = (uint4*)g_h1[bx];
            for (int i = tid; i < H1BINS / 4; i += NTHREADS) h4[i] = z;
        }
        for (int i = tid; i < 2 * NBINS; i += NTHREADS) g_softG[bx][i] = 0.0f;
    } else {
        const uint4* pp = (const uint4*)pred;
        int quads = (nper * BATCH) >> 2;
        unsigned acc = 0u;
        for (int i = (bx - BATCH) * NTHREADS + tid; i < quads;
             i += (NBLOCKS - BATCH) * NTHREADS) {
            uint4 v = pp[i];
            acc ^= v.x ^ v.y ^ v.z ^ v.w;
        }
        g_dummy[bx] = acc;
    }
    grid_sync();

    // ================= P3: collect candidates (~3% match) ================
    {
        unsigned b0 = g_tinfo[samp][0], b1 = g_tinfo[samp][2];
        bool two = (b0 != b1);
        int wbase0 = sblk * NTHREADS + warp * 32;
        for (int base = wbase0; base < nq; base += istr) {
            int i = base + lane;
            bool v = (i < nq);
            float4 val;
            if (v) val = g4[i];
            unsigned kk[4] = {v ? __float_as_uint(val.x) : SKIP,
                              v ? __float_as_uint(val.y) : SKIP,
                              v ? __float_as_uint(val.z) : SKIP,
                              v ? __float_as_uint(val.w) : SKIP};
            #pragma unroll
            for (int c = 0; c < 4; c++) {
                unsigned t = kk[c] >> 19;
                wpush(v && t == b0, kk[c], &g_ccnt[samp][0], g_cand[samp][0], lane);
                if (two)
                    wpush(v && t == b1, kk[c], &g_ccnt[samp][1], g_cand[samp][1], lane);
            }
        }
        for (int base = (nq << 2) + sblk * NTHREADS + warp * 32; base < nper;
             base += istr) {
            int i = base + lane;
            bool v = (i < nper);
            unsigned kk = v ? __float_as_uint(gb[i]) : SKIP;
            unsigned t = kk >> 19;
            wpush(v && t == b0, kk, &g_ccnt[samp][0], g_cand[samp][0], lane);
            if (two)
                wpush(v && t == b1, kk, &g_ccnt[samp][1], g_cand[samp][1], lane);
        }
    }
    grid_sync();

    // ================= P4: select (blocks 0-7: one per sample x rank) ====
    if (bx < 2 * BATCH) {
        int s = bx >> 1, r = bx & 1;
        unsigned B0 = g_tinfo[s][0], B1 = g_tinfo[s][2];
        bool two = (B0 != B1);
        unsigned myBin = r ? B1 : B0;
        unsigned myRem = r ? g_tinfo[s][3] : g_tinfo[s][1];
        int bufI = (two && r) ? 1 : 0;
        unsigned c = g_ccnt[s][bufI];
        const unsigned* buf = g_cand[s][bufI];

        // level A: bits 18..8 (2048 bins)
        for (int i = tid; i < RA; i += NTHREADS) sh[i] = 0u;
        __syncthreads();
        for (unsigned i = tid; i < c; i += NTHREADS)
            atomicAdd(&sh[(buf[i] >> 8) & 0x7FFu], 1u);
        __syncthreads();
        locate2(sh, RA, myRem, SKIP, s_ws, s_loc);
        unsigned a = s_loc[0], ra = s_loc[1];
        __syncthreads();

        // level B: bits 7..0 (256 bins)
        for (int i = tid; i < RB; i += NTHREADS) sh[i] = 0u;
        __syncthreads();
        for (unsigned i = tid; i < c; i += NTHREADS) {
            unsigned kk = buf[i];
            if (((kk >> 8) & 0x7FFu) == a) atomicAdd(&sh[kk & 0xFFu], 1u);
        }
        __syncthreads();
        locate2(sh, RB, ra, SKIP, s_ws, s_loc);
        unsigned cc = s_loc[0];
        if (tid == 0)
            g_val[s][r] = __uint_as_float((myBin << 19) | (a << 8) | cc);
    }
    grid_sync();

    // ================= P5: soft hists, global float RED flush =============
    {
        float v0 = g_val[samp][0], v1 = g_val[samp][1];
        float mv = v0 + frac * (v1 - v0);
        float invbw = (mv > 0.0f) ? (float)NBINS / mv : 0.0f;
        float* shf = (float*)sh;
        for (int i = tid; i < 4 * 2 * NBINS; i += NTHREADS) shf[i] = 0.0f;
        __syncthreads();
        float* my = shf + (warp & 3) * 2 * NBINS;
        const float4* p4 = (const float4*)(pred + (size_t)samp * nper);
        for (int i = i0; i < nq; i += istr) {
            float4 pv = p4[i];
            float4 gv = g4[i];
            float pe[4] = {pv.x, pv.y, pv.z, pv.w};
            float ge[4] = {gv.x, gv.y, gv.z, gv.w};
            #pragma unroll
            for (int cx = 0; cx < 4; cx++) {
                float up = pe[cx] * invbw;
                int   jp = (int)floorf(up);
                float fp = up - (float)jp;
                if (jp >= 0 && jp < NBINS) {
                    atomicAdd(&my[jp], 1.0f - fp);
                    if (jp + 1 < NBINS) atomicAdd(&my[jp + 1], fp);
                }
                float ug = ge[cx] * invbw;
                int   jg = (int)floorf(ug);
                float fg = ug - (float)jg;
                if (jg >= 0 && jg < NBINS) {
                    atomicAdd(&my[NBINS + jg], 1.0f - fg);
                    if (jg + 1 < NBINS) atomicAdd(&my[NBINS + jg + 1], fg);
                }
            }
        }
        const float* pb = pred + (size_t)samp * nper;
        for (int i = tail0; i < nper; i += istr) {
            float up = pb[i] * invbw;
            int   jp = (int)floorf(up);
            float fp = up - (float)jp;
            if (jp >= 0 && jp < NBINS) {
                atomicAdd(&my[jp], 1.0f - fp);
                if (jp + 1 < NBINS) atomicAdd(&my[jp + 1], fp);
            }
            float ug = gb[i] * invbw;
            int   jg = (int)floorf(ug);
            float fg = ug - (float)jg;
            if (jg >= 0 && jg < NBINS) {
                atomicAdd(&my[NBINS + jg], 1.0f - fg);
                if (jg + 1 < NBINS) atomicAdd(&my[NBINS + jg + 1], fg);
            }
        }
        __syncthreads();
        for (int i = tid; i < 2 * NBINS; i += NTHREADS) {
            float v = shf[i] + shf[128 + i] + shf[256 + i] + shf[384 + i];
            if (v != 0.0f) atomicAdd(&g_softG[samp][i], v);
        }
    }
    grid_sync();

    // ================= P6: finalize (block 0) =============================
    if (bx == 0) {
        float* s_h = (float*)sh;           // 512 floats: [b][0..127]
        if (tid < BATCH * 2 * NBINS) {
            int b = tid >> 7, idx = tid & 127;
            s_h[tid] = g_softG[b][idx];
        }
        __syncthreads();
        if (warp < BATCH) {
            int b = warp;
            float sp = s_h[b * 128 + lane] + s_h[b * 128 + 32 + lane];
            float sg = s_h[b * 128 + 64 + lane] + s_h[b * 128 + 96 + lane];
            #pragma unroll
            for (int o = 16; o >= 1; o >>= 1) {
                sp += __shfl_xor_sync(FULLM, sp, o);
                sg += __shfl_xor_sync(FULLM, sg, o);
            }
            float acc = 0.0f;
            #pragma unroll
            for (int h = 0; h < 2; h++) {
                int j = h * 32 + lane;
                float bw = expf(0.4f * (float)j / (float)NBINS);
                float p = s_h[b * 128 + j];
                float g = s_h[b * 128 + 64 + j];
                acc += fabsf(p / sp - g / sg) * bw;
            }
            #pragma unroll
            for (int o = 16; o >= 1; o >>= 1)
                acc += __shfl_xor_sync(FULLM, acc, o);
            if (lane == 0) s_red[b] = acc * (1.0f / (float)NBINS);
        }
        __syncthreads();
        if (tid == 0)
            out[0] = (s_red[0] + s_red[1] + s_red[2] + s_red[3]) *
                     (1.0f / (float)BATCH);
    }
}

// -------------------------------------------------------------------------
extern "C" void kernel_launch(void* const* d_in, const int* in_sizes, int n_in,
                              void* d_out, int out_size) {
    const float* pred = (const float*)d_in[0];
    const float* gt   = (const float*)d_in[1];
    int ntot = in_sizes[0];
    int nper = ntot / BATCH;

    double pos = 0.95 * (double)(nper - 1);
    unsigned k = (unsigned)pos;
    float frac = (float)(pos - (double)k);

    ghl_kernel<<<NBLOCKS, NTHREADS>>>(pred, gt, nper, k, frac, (float*)d_out);
}

// round 12
// speedup vs baseline: 2.2135x; 1.6502x over previous
#include <cuda_runtime.h>
#include <math.h>

// GradientHistLoss — persistent kernel, 148x1024, 32KB smem, 3 grid syncs.
// Quantile via two-level histogram refinement (13 + 12 bits = 25-bit prefix,
// midpoint reconstruction; relative error <= 7.6e-6, far inside the 1e-3
// correctness budget). No candidate collection, no dedicated select blocks.
//  P1  all: 13-bit shared hist of gt -> sparse RED flush; prefetch pred to L2.
//  P2  all: redundant locate ranks k,k+1 on global hist; refined 12-bit hist
//      (two prefix filters) over own stripe -> sparse RED flush.
//  P3  all: redundant locate refined bins -> invbw; triangular soft hists
//      (pred+gt) -> global float RED.
//  P4  blk0: finalize -> out;  all: re-zero global hists for next replay.

#define NBINS    64
#define BATCH    4
#define NBLOCKS  148
#define NTHREADS 1024
#define SBLKS    37
#define H1       8192          // key >> 19
#define H2       4096          // (key >> 7) & 0xFFF
#define SKIP     0xFFFFFFFFu
#define FULLM    0xFFFFFFFFu

// ---- device scratch (zero at load; re-zeroed in P4 each call) ----
__device__ unsigned g_h1[BATCH][H1];
__device__ unsigned g_h2[BATCH][2][H2];
__device__ float    g_softG[BATCH][2 * NBINS];
__device__ unsigned g_dummy[NBLOCKS];
__device__ unsigned          g_bar_count;
__device__ volatile unsigned g_bar_gen;

// -------------------------------------------------------------------------
__device__ __forceinline__ void grid_sync() {
    __syncthreads();
    if (threadIdx.x == 0) {
        __threadfence();
        unsigned gen = g_bar_gen;
        if (atomicAdd(&g_bar_count, 1u) == NBLOCKS - 1) {
            g_bar_count = 0u;
            __threadfence();
            g_bar_gen = gen + 1u;
        } else {
            while (g_bar_gen == gen) { __nanosleep(20); }
        }
        __threadfence();
    }
    __syncthreads();
}

// Block-collective: locate ranks r0 (and r1 unless SKIP) in cnt[0..bins).
// Results broadcast via s_loc = {bin0, rem0, bin1, rem1}.
__device__ void locate2(const unsigned* cnt, int bins, unsigned r0, unsigned r1,
                        unsigned* s_ws, unsigned* s_loc) {
    int tid = threadIdx.x, lane = tid & 31, warp = tid >> 5;
    int per = bins / NTHREADS;             // 8 or 4
    int base = tid * per;
    unsigned sum = 0u;
    for (int i = 0; i < per; i++) sum += cnt[base + i];
    unsigned incl = sum;
    #pragma unroll
    for (int o = 1; o < 32; o <<= 1) {
        unsigned v = __shfl_up_sync(FULLM, incl, o);
        if (lane >= o) incl += v;
    }
    if (lane == 31) s_ws[warp] = incl;
    __syncthreads();
    if (warp == 0) {
        unsigned v = s_ws[lane], wi = v;
        #pragma unroll
        for (int o = 1; o < 32; o <<= 1) {
            unsigned t = __shfl_up_sync(FULLM, wi, o);
            if (lane >= o) wi += t;
        }
        s_ws[lane] = wi - v;
    }
    __syncthreads();
    unsigned inclT = incl + s_ws[warp];
    unsigned exclT = inclT - sum;
    #pragma unroll
    for (int j = 0; j < 2; j++) {
        unsigned r = (j == 0) ? r0 : r1;
        if (r != SKIP && exclT <= r && r < inclT) {
            unsigned local = r - exclT;
            int d = base;
            while (local >= cnt[d]) { local -= cnt[d]; d++; }
            s_loc[2 * j] = (unsigned)d;
            s_loc[2 * j + 1] = local;
        }
    }
    __syncthreads();
}

// -------------------------------------------------------------------------
__global__ void __launch_bounds__(NTHREADS, 1)
ghl_kernel(const float* __restrict__ pred, const float* __restrict__ gt,
           int nper, unsigned k, float frac, float* __restrict__ out) {
    __shared__ unsigned sh[H1];            // 32KB, reused per phase
    __shared__ unsigned s_ws[32];
    __shared__ unsigned s_loc[4];
    __shared__ float    s_red[BATCH];

    int tid  = threadIdx.x;
    int lane = tid & 31;
    int warp = tid >> 5;
    int bx   = blockIdx.x;
    int samp = bx & 3;
    int sblk = bx >> 2;
    const float*  gb = gt + (size_t)samp * nper;
    const float4* g4 = (const float4*)gb;
    int nq    = nper >> 2;
    int i0    = sblk * NTHREADS + tid;
    int istr  = SBLKS * NTHREADS;
    int tail0 = (nq << 2) + i0;

    // ================= P1: 13-bit hist of gt + prefetch pred =============
    for (int i = tid; i < H1; i += NTHREADS) sh[i] = 0u;
    __syncthreads();
    for (int i = i0; i < nq; i += istr) {
        float4 v = g4[i];
        atomicAdd(&sh[__float_as_uint(v.x) >> 19], 1u);
        atomicAdd(&sh[__float_as_uint(v.y) >> 19], 1u);
        atomicAdd(&sh[__float_as_uint(v.z) >> 19], 1u);
        atomicAdd(&sh[__float_as_uint(v.w) >> 19], 1u);
    }
    for (int i = tail0; i < nper; i += istr)
        atomicAdd(&sh[__float_as_uint(gb[i]) >> 19], 1u);
    {   // prefetch all of pred into L2 (overlaps with hist DRAM traffic)
        const uint4* pp = (const uint4*)pred;
        int quads = (nper * BATCH) >> 2;
        unsigned acc = 0u;
        for (int i = bx * NTHREADS + tid; i < quads; i += NBLOCKS * NTHREADS) {
            uint4 v = pp[i];
            acc ^= v.x ^ v.y ^ v.z ^ v.w;
        }
        g_dummy[bx] = acc;
    }
    __syncthreads();
    for (int i = tid; i < H1; i += NTHREADS) {
        unsigned v = sh[i];
        if (v) atomicAdd(&g_h1[samp][i], v);
    }
    grid_sync();

    // ================= P2: locate (redundant) + refined 12-bit hist =======
    locate2(g_h1[samp], H1, k, k + 1u, s_ws, s_loc);
    unsigned b0 = s_loc[0], rem0 = s_loc[1];
    unsigned b1 = s_loc[2], rem1 = s_loc[3];
    bool two = (b1 != b0);
    {
        unsigned* sh2a = sh;
        unsigned* sh2b = sh + H2;
        for (int i = tid; i < 2 * H2; i += NTHREADS) sh[i] = 0u;
        __syncthreads();
        for (int i = i0; i < nq; i += istr) {
            float4 v = g4[i];
            unsigned kk[4] = {__float_as_uint(v.x), __float_as_uint(v.y),
                              __float_as_uint(v.z), __float_as_uint(v.w)};
            #pragma unroll
            for (int c = 0; c < 4; c++) {
                unsigned p = kk[c] >> 19;
                if (p == b0)      atomicAdd(&sh2a[(kk[c] >> 7) & 0xFFFu], 1u);
                else if (p == b1) atomicAdd(&sh2b[(kk[c] >> 7) & 0xFFFu], 1u);
            }
        }
        for (int i = tail0; i < nper; i += istr) {
            unsigned kk = __float_as_uint(gb[i]);
            unsigned p = kk >> 19;
            if (p == b0)      atomicAdd(&sh2a[(kk >> 7) & 0xFFFu], 1u);
            else if (p == b1) atomicAdd(&sh2b[(kk >> 7) & 0xFFFu], 1u);
        }
        __syncthreads();
        for (int i = tid; i < H2; i += NTHREADS) {
            unsigned va = sh2a[i];
            if (va) atomicAdd(&g_h2[samp][0][i], va);
            if (two) {
                unsigned vb = sh2b[i];
                if (vb) atomicAdd(&g_h2[samp][1][i], vb);
            }
        }
    }
    grid_sync();

    // ================= P3: refined locate (redundant) + soft hists ========
    {
        unsigned a0, a1;
        if (!two) {
            locate2(g_h2[samp][0], H2, rem0, rem1, s_ws, s_loc);
            a0 = s_loc[0]; a1 = s_loc[2];
        } else {
            locate2(g_h2[samp][0], H2, rem0, SKIP, s_ws, s_loc);
            a0 = s_loc[0];
            locate2(g_h2[samp][1], H2, rem1, SKIP, s_ws, s_loc);
            a1 = s_loc[0];
        }
        // midpoint of the 25-bit prefix bin: rel. error <= 7.6e-6
        float v0 = __uint_as_float((b0 << 19) | (a0 << 7) | 0x40u);
        float v1 = __uint_as_float((b1 << 19) | (a1 << 7) | 0x40u);
        float mv = v0 + frac * (v1 - v0);
        float invbw = (mv > 0.0f) ? (float)NBINS / mv : 0.0f;

        float* shf = (float*)sh;
        for (int i = tid; i < 4 * 2 * NBINS; i += NTHREADS) shf[i] = 0.0f;
        __syncthreads();
        float* my = shf + (warp & 3) * 2 * NBINS;
        const float4* p4 = (const float4*)(pred + (size_t)samp * nper);
        for (int i = i0; i < nq; i += istr) {
            float4 pv = p4[i];
            float4 gv = g4[i];
            float pe[4] = {pv.x, pv.y, pv.z, pv.w};
            float ge[4] = {gv.x, gv.y, gv.z, gv.w};
            #pragma unroll
            for (int c = 0; c < 4; c++) {
                float up = pe[c] * invbw;
                int   jp = (int)floorf(up);
                float fp = up - (float)jp;
                if (jp >= 0 && jp < NBINS) {
                    atomicAdd(&my[jp], 1.0f - fp);
                    if (jp + 1 < NBINS) atomicAdd(&my[jp + 1], fp);
                }
                float ug = ge[c] * invbw;
                int   jg = (int)floorf(ug);
                float fg = ug - (float)jg;
                if (jg >= 0 && jg < NBINS) {
                    atomicAdd(&my[NBINS + jg], 1.0f - fg);
                    if (jg + 1 < NBINS) atomicAdd(&my[NBINS + jg + 1], fg);
                }
            }
        }
        const float* pb = pred + (size_t)samp * nper;
        for (int i = tail0; i < nper; i += istr) {
            float up = pb[i] * invbw;
            int   jp = (int)floorf(up);
            float fp = up - (float)jp;
            if (jp >= 0 && jp < NBINS) {
                atomicAdd(&my[jp], 1.0f - fp);
                if (jp + 1 < NBINS) atomicAdd(&my[jp + 1], fp);
            }
            float ug = gb[i] * invbw;
            int   jg = (int)floorf(ug);
            float fg = ug - (float)jg;
            if (jg >= 0 && jg < NBINS) {
                atomicAdd(&my[NBINS + jg], 1.0f - fg);
                if (jg + 1 < NBINS) atomicAdd(&my[NBINS + jg + 1], fg);
            }
        }
        __syncthreads();
        for (int i = tid; i < 2 * NBINS; i += NTHREADS) {
            float v = shf[i] + shf[128 + i] + shf[256 + i] + shf[384 + i];
            if (v != 0.0f) atomicAdd(&g_softG[samp][i], v);
        }
    }
    grid_sync();

    // ================= P4: finalize (blk0) + re-zero hists (all) ==========
    {   // cooperative zero of g_h1 (32K ints) + g_h2 (32K ints), uint4-wide
        uint4 z = {0u, 0u, 0u, 0u};
        uint4* h1 = (uint4*)g_h1;
        uint4* h2 = (uint4*)g_h2;
        int n1 = (BATCH * H1) / 4, n2 = (BATCH * 2 * H2) / 4;
        for (int i = bx * NTHREADS + tid; i < n1; i += NBLOCKS * NTHREADS)
            h1[i] = z;
        for (int i = bx * NTHREADS + tid; i < n2; i += NBLOCKS * NTHREADS)
            h2[i] = z;
    }
    if (bx == 0) {
        float* s_h = (float*)sh;           // 512 floats: [b][0..127]
        if (tid < BATCH * 2 * NBINS) {
            int b = tid >> 7, idx = tid & 127;
            s_h[tid] = g_softG[b][idx];
        }
        __syncthreads();
        if (warp < BATCH) {
            int b = warp;
            float sp = s_h[b * 128 + lane] + s_h[b * 128 + 32 + lane];
            float sg = s_h[b * 128 + 64 + lane] + s_h[b * 128 + 96 + lane];
            #pragma unroll
            for (int o = 16; o >= 1; o >>= 1) {
                sp += __shfl_xor_sync(FULLM, sp, o);
                sg += __shfl_xor_sync(FULLM, sg, o);
            }
            float acc = 0.0f;
            #pragma unroll
            for (int h = 0; h < 2; h++) {
                int j = h * 32 + lane;
                float bw = expf(0.4f * (float)j / (float)NBINS);
                float p = s_h[b * 128 + j];
                float g = s_h[b * 128 + 64 + j];
                acc += fabsf(p / sp - g / sg) * bw;
            }
            #pragma unroll
            for (int o = 16; o >= 1; o >>= 1)
                acc += __shfl_xor_sync(FULLM, acc, o);
            if (lane == 0) s_red[b] = acc * (1.0f / (float)NBINS);
        }
        __syncthreads();
        if (tid == 0)
            out[0] = (s_red[0] + s_red[1] + s_red[2] + s_red[3]) *
                     (1.0f / (float)BATCH);
        __syncthreads();
        // zero soft accumulators for next replay (after reads above)
        for (int i = tid; i < BATCH * 2 * NBINS; i += NTHREADS)
            ((float*)g_softG)[i] = 0.0f;
    }
}

// -------------------------------------------------------------------------
extern "C" void kernel_launch(void* const* d_in, const int* in_sizes, int n_in,
                              void* d_out, int out_size) {
    const float* pred = (const float*)d_in[0];
    const float* gt   = (const float*)d_in[1];
    int ntot = in_sizes[0];
    int nper = ntot / BATCH;

    double pos = 0.95 * (double)(nper - 1);
    unsigned k = (unsigned)pos;
    float frac = (float)(pos - (double)k);

    ghl_kernel<<<NBLOCKS, NTHREADS>>>(pred, gt, nper, k, frac, (float*)d_out);
}